// round 15
// baseline (speedup 1.0000x reference)
#include <cuda_runtime.h>
#include <cstdint>

// B=256,H=32,S=16,D=64 -> 8192 heads. out = dropout(softmax(QK^T/sqrt8)) @ V
// (all-ones additive mask is softmax-invariant; dropout = JAX partitionable
//  threefry key (0,42): keep iff bits < 0xB3333400 (u<0.7), scale 1/0.7).
//
// R15 = R14 with (a) padded pitch-68 smem (no XOR swizzle -> cheap affine
//       addressing, same 1-phase banks), (b) persistent 1-wave grid (1924
//       CTAs, 2-3 units each) to kill the fractional-wave tail.

#define NTHREADS 32
#define HPC 2                  // heads per unit (= per warp iteration)
#define NUNITS 4096            // 8192 heads / HPC
#define PGRID 1924             // 148 SMs * 13 resident CTAs = one full wave
#define PITCH 68               // row pitch in floats
#define HSTR 1104              // per-head floats (16*68 + 16)
#define H_U2 256               // 16B units per head (1024 floats)

typedef unsigned long long ull;

__device__ __forceinline__ ull pack2dup(float x) {
    ull r; asm("mov.b64 %0, {%1,%1};" : "=l"(r) : "f"(x)); return r;
}
__device__ __forceinline__ float2 unpack2(ull p) {
    float2 v; asm("mov.b64 {%0,%1}, %2;" : "=f"(v.x), "=f"(v.y) : "l"(p)); return v;
}
__device__ __forceinline__ ull fma2(ull a, ull b, ull c) {
    ull d; asm("fma.rn.f32x2 %0, %1, %2, %3;" : "=l"(d) : "l"(a), "l"(b), "l"(c)); return d;
}
__device__ __forceinline__ unsigned rotl32(unsigned x, int d) {
    return (x << d) | (x >> (32 - d));
}

// JAX threefry2x32, key=(0,42), counts (0, lin0+4c) c=0..3, 4 chains (ILP).
__device__ __forceinline__ unsigned tf_keep4(unsigned lin0) {
    const unsigned k1 = 42u;
    const unsigned k2 = 42u ^ 0x1BD11BDAu;
    unsigned x0[4], x1[4];
#pragma unroll
    for (int c = 0; c < 4; c++) { x0[c] = 0u; x1[c] = lin0 + 4u * c + k1; }

#define TFR4(r) { _Pragma("unroll") for (int c = 0; c < 4; c++) { \
    x0[c] += x1[c]; x1[c] = rotl32(x1[c], r); x1[c] ^= x0[c]; } }
#define INJ4(a, b) { _Pragma("unroll") for (int c = 0; c < 4; c++) { \
    x0[c] += (a); x1[c] += (b); } }

    TFR4(13) TFR4(15) TFR4(26) TFR4(6)   INJ4(k1, k2 + 1u)
    TFR4(17) TFR4(29) TFR4(16) TFR4(24)  INJ4(k2, 2u)
    TFR4(13) TFR4(15) TFR4(26) TFR4(6)   INJ4(0u, k1 + 3u)
    TFR4(17) TFR4(29) TFR4(16) TFR4(24)  INJ4(k1, k2 + 4u)
    TFR4(13) TFR4(15) TFR4(26) TFR4(6)   INJ4(k2, 5u)
#undef TFR4
#undef INJ4

    unsigned m = 0;
#pragma unroll
    for (int c = 0; c < 4; c++)
        m |= ((x0[c] ^ x1[c]) < 0xB3333400u ? 1u : 0u) << c;
    return m;
}

__global__ __launch_bounds__(NTHREADS, 13)
void attn_dropout_kernel(const float* __restrict__ q,
                         const float* __restrict__ k,
                         const float* __restrict__ v,
                         float* __restrict__ out) {
    __shared__ __align__(16) float sQV[HPC * HSTR];  // Q, later reused for V
    __shared__ __align__(16) float sK[HPC * HSTR];

    const int tid  = threadIdx.x;       // 0..31
    const int hloc = tid >> 4;          // local head 0/1
    const int hl   = tid & 15;
    const int s_blk = hl & 3;           // rows s_blk + 4k
    const int t_blk = hl >> 2;          // cols t_blk + 4m
    const float SCALE = 0.35355339059327373f;   // 1/sqrt(8)

    const float4* gq = reinterpret_cast<const float4*>(q);
    const float4* gk = reinterpret_cast<const float4*>(k);
    const float4* gv = reinterpret_cast<const float4*>(v);

    for (int unit = blockIdx.x; unit < NUNITS; unit += PGRID) {
        const int head  = unit * HPC + hloc;
        const int base4 = unit * (HPC * 256);

        __syncwarp();   // prior-iter epilogue reads of sQV/sK complete

        // ---- Stage Q, K into padded smem (coalesced LDG.128) ----
#pragma unroll
        for (int j = 0; j < (HPC * 256) / NTHREADS; j++) {
            int idx = j * NTHREADS + tid;     // float4 index within unit, 0..511
            int hh  = idx >> 8;
            int rem = idx & 255;              // row*16 + c
            int off = hh * HSTR + (rem >> 4) * PITCH + (rem & 15) * 4;
            float4 qv = gq[base4 + idx];
            float4 kv = gk[base4 + idx];
            *reinterpret_cast<float4*>(&sQV[off]) = qv;
            *reinterpret_cast<float4*>(&sK[off]) = kv;
        }

        // ---- Dropout bits: 4 groups x 4 interleaved chains (hides LDG) ----
        unsigned keepmask = 0;
        {
            unsigned base = (unsigned)head * 256u + (unsigned)(s_blk * 16 + t_blk);
#pragma unroll 1
            for (int kk = 0; kk < 4; kk++)
                keepmask |= tf_keep4(base + 64u * (unsigned)kk) << (4 * kk);
        }

        __syncwarp();

        // ---- Scores: 4x4 tile per thread, padded smem (1 phase/instr) ----
        const float* qb = sQV + hloc * HSTR + s_blk * PITCH;
        const float* kb = sK  + hloc * HSTR + t_blk * PITCH;
        ull acc[4][4];
#pragma unroll
        for (int kk = 0; kk < 4; kk++)
#pragma unroll
            for (int mm = 0; mm < 4; mm++) acc[kk][mm] = 0ull;

#pragma unroll
        for (int i = 0; i < 16; i++) {
            ulonglong2 q2[4], k2[4];
#pragma unroll
            for (int kk = 0; kk < 4; kk++)
                q2[kk] = *reinterpret_cast<const ulonglong2*>(qb + kk * (4 * PITCH) + 4 * i);
#pragma unroll
            for (int mm = 0; mm < 4; mm++)
                k2[mm] = *reinterpret_cast<const ulonglong2*>(kb + mm * (4 * PITCH) + 4 * i);
#pragma unroll
            for (int kk = 0; kk < 4; kk++)
#pragma unroll
                for (int mm = 0; mm < 4; mm++) {
                    acc[kk][mm] = fma2(q2[kk].x, k2[mm].x, acc[kk][mm]);
                    acc[kk][mm] = fma2(q2[kk].y, k2[mm].y, acc[kk][mm]);
                }
        }

        // ---- Issue ALL V loads now (latency overlapped by softmax) ----
        float4 vreg[16];
#pragma unroll
        for (int j = 0; j < 16; j++)
            vreg[j] = gv[base4 + j * NTHREADS + tid];

        __syncwarp();   // all lanes done reading Q region before it becomes V

        // ---- Softmax per row (4 local + xor-shuffle over t_blk) + dropout ----
        float w[4][4];
#pragma unroll
        for (int kk = 0; kk < 4; kk++) {
            float e[4], sum = 0.f;
#pragma unroll
            for (int mm = 0; mm < 4; mm++) {
                float2 p = unpack2(acc[kk][mm]);
                e[mm] = __expf((p.x + p.y) * SCALE);   // logits ~N(0,8): skip max-sub
                sum += e[mm];
            }
            sum += __shfl_xor_sync(0xffffffffu, sum, 4, 16);
            sum += __shfl_xor_sync(0xffffffffu, sum, 8, 16);
            float inv = __fdividef(1.4285714285714286f, sum);   // (1/0.7)/sum
#pragma unroll
            for (int mm = 0; mm < 4; mm++)
                w[kk][mm] = ((keepmask >> (kk * 4 + mm)) & 1u) ? e[mm] * inv : 0.f;
        }

        // ---- Park V into the dead Q smem region (same padded layout) ----
#pragma unroll
        for (int j = 0; j < 16; j++) {
            int idx = j * NTHREADS + tid;
            int rem = idx & 255;
            int off = (idx >> 8) * HSTR + (rem >> 4) * PITCH + (rem & 15) * 4;
            *reinterpret_cast<float4*>(&sQV[off]) = vreg[j];
        }
        __syncwarp();

        // ---- Epilogue: all-LDS, two passes over quad pairs (regs) ----
        ulonglong2* og = reinterpret_cast<ulonglong2*>(out) + (size_t)head * H_U2;
        const float* vb = sQV + hloc * HSTR;

#pragma unroll 1
        for (int pass = 0; pass < 2; pass++) {
            ull olo[4][2], ohi[4][2];             // rows s_blk+4k x quads t_blk+4(2p+c)
#pragma unroll
            for (int kk = 0; kk < 4; kk++)
#pragma unroll
                for (int cc = 0; cc < 2; cc++) { olo[kk][cc] = 0ull; ohi[kk][cc] = 0ull; }

#pragma unroll
            for (int t = 0; t < 16; t++) {
                int src = s_blk + 4 * (t & 3);    // lane holding w[.][t>>2] for our rows
                ull wp[4];
#pragma unroll
                for (int kk = 0; kk < 4; kk++)
                    wp[kk] = pack2dup(__shfl_sync(0xffffffffu, w[kk][t >> 2], src, 16));
#pragma unroll
                for (int cc = 0; cc < 2; cc++) {
                    ulonglong2 vv = *reinterpret_cast<const ulonglong2*>(
                        vb + t * PITCH + (t_blk + 4 * (2 * pass + cc)) * 4);
#pragma unroll
                    for (int kk = 0; kk < 4; kk++) {
                        olo[kk][cc] = fma2(wp[kk], vv.x, olo[kk][cc]);
                        ohi[kk][cc] = fma2(wp[kk], vv.y, ohi[kk][cc]);
                    }
                }
            }

#pragma unroll
            for (int kk = 0; kk < 4; kk++)
#pragma unroll
                for (int cc = 0; cc < 2; cc++) {
                    ulonglong2 val; val.x = olo[kk][cc]; val.y = ohi[kk][cc];
                    og[(s_blk + 4 * kk) * 16 + t_blk + 4 * (2 * pass + cc)] = val;
                }
        }
    }
}

extern "C" void kernel_launch(void* const* d_in, const int* in_sizes, int n_in,
                              void* d_out, int out_size) {
    const float* q = (const float*)d_in[0];
    const float* k = (const float*)d_in[1];
    const float* v = (const float*)d_in[2];
    float* out = (float*)d_out;
    attn_dropout_kernel<<<PGRID, NTHREADS>>>(q, k, v, out);
}

// round 16
// speedup vs baseline: 1.2063x; 1.2063x over previous
#include <cuda_runtime.h>
#include <cstdint>

// B=256,H=32,S=16,D=64 -> 8192 heads. out = dropout(softmax(QK^T/sqrt8)) @ V
// (all-ones additive mask is softmax-invariant; dropout = JAX partitionable
//  threefry key (0,42): keep iff bits < 0xB3333400 (u<0.7), scale 1/0.7).
//
// R16: fused single kernel, grid of 4096 independent 1-warp CTAs (2 heads
//      per warp, 16 thr/head, 4x4 tiles). Padded pitch-68 smem (cheap affine
//      addressing, 1-phase banks). ILP-4 inline threefry. V loaded during
//      softmax, parked in dead Q smem. SINGLE-pass epilogue (64 shfl not 128).

#define NTHREADS 32
#define HPC 2                  // heads per CTA (= per warp)
#define PITCH 68               // row pitch in floats
#define HSTR 1104              // per-head floats (16*68 + 16)
#define H_U2 256               // 16B units per head (1024 floats)

typedef unsigned long long ull;

__device__ __forceinline__ ull pack2dup(float x) {
    ull r; asm("mov.b64 %0, {%1,%1};" : "=l"(r) : "f"(x)); return r;
}
__device__ __forceinline__ float2 unpack2(ull p) {
    float2 v; asm("mov.b64 {%0,%1}, %2;" : "=f"(v.x), "=f"(v.y) : "l"(p)); return v;
}
__device__ __forceinline__ ull fma2(ull a, ull b, ull c) {
    ull d; asm("fma.rn.f32x2 %0, %1, %2, %3;" : "=l"(d) : "l"(a), "l"(b), "l"(c)); return d;
}
__device__ __forceinline__ unsigned rotl32(unsigned x, int d) {
    return (x << d) | (x >> (32 - d));
}

// JAX threefry2x32, key=(0,42), counts (0, lin0+4c) c=0..3, 4 chains (ILP).
__device__ __forceinline__ unsigned tf_keep4(unsigned lin0) {
    const unsigned k1 = 42u;
    const unsigned k2 = 42u ^ 0x1BD11BDAu;
    unsigned x0[4], x1[4];
#pragma unroll
    for (int c = 0; c < 4; c++) { x0[c] = 0u; x1[c] = lin0 + 4u * c + k1; }

#define TFR4(r) { _Pragma("unroll") for (int c = 0; c < 4; c++) { \
    x0[c] += x1[c]; x1[c] = rotl32(x1[c], r); x1[c] ^= x0[c]; } }
#define INJ4(a, b) { _Pragma("unroll") for (int c = 0; c < 4; c++) { \
    x0[c] += (a); x1[c] += (b); } }

    TFR4(13) TFR4(15) TFR4(26) TFR4(6)   INJ4(k1, k2 + 1u)
    TFR4(17) TFR4(29) TFR4(16) TFR4(24)  INJ4(k2, 2u)
    TFR4(13) TFR4(15) TFR4(26) TFR4(6)   INJ4(0u, k1 + 3u)
    TFR4(17) TFR4(29) TFR4(16) TFR4(24)  INJ4(k1, k2 + 4u)
    TFR4(13) TFR4(15) TFR4(26) TFR4(6)   INJ4(k2, 5u)
#undef TFR4
#undef INJ4

    unsigned m = 0;
#pragma unroll
    for (int c = 0; c < 4; c++)
        m |= ((x0[c] ^ x1[c]) < 0xB3333400u ? 1u : 0u) << c;
    return m;
}

__global__ __launch_bounds__(NTHREADS, 11)
void attn_dropout_kernel(const float* __restrict__ q,
                         const float* __restrict__ k,
                         const float* __restrict__ v,
                         float* __restrict__ out) {
    __shared__ __align__(16) float sQV[HPC * HSTR];  // Q, later reused for V
    __shared__ __align__(16) float sK[HPC * HSTR];

    const int tid  = threadIdx.x;       // 0..31
    const int hloc = tid >> 4;          // local head 0/1
    const int hl   = tid & 15;
    const int s_blk = hl & 3;           // rows s_blk + 4k
    const int t_blk = hl >> 2;          // cols t_blk + 4m
    const int head  = blockIdx.x * HPC + hloc;
    const float SCALE = 0.35355339059327373f;   // 1/sqrt(8)

    // ---- Stage Q, K into padded smem (coalesced LDG.128) ----
    {
        const float4* gq = reinterpret_cast<const float4*>(q);
        const float4* gk = reinterpret_cast<const float4*>(k);
        const int base4 = blockIdx.x * (HPC * 256);
#pragma unroll
        for (int j = 0; j < (HPC * 256) / NTHREADS; j++) {
            int idx = j * NTHREADS + tid;     // float4 index within CTA, 0..511
            int rem = idx & 255;              // row*16 + c
            int off = (idx >> 8) * HSTR + (rem >> 4) * PITCH + (rem & 15) * 4;
            float4 qv = gq[base4 + idx];
            float4 kv = gk[base4 + idx];
            *reinterpret_cast<float4*>(&sQV[off]) = qv;
            *reinterpret_cast<float4*>(&sK[off]) = kv;
        }
    }

    // ---- Dropout bits: 4 groups x 4 interleaved chains (hides staging LDG) ----
    unsigned keepmask = 0;
    {
        unsigned base = (unsigned)head * 256u + (unsigned)(s_blk * 16 + t_blk);
#pragma unroll 1
        for (int kk = 0; kk < 4; kk++)
            keepmask |= tf_keep4(base + 64u * (unsigned)kk) << (4 * kk);
    }

    __syncwarp();

    // ---- Scores: 4x4 tile per thread, padded smem (1 phase/instr) ----
    const float* qb = sQV + hloc * HSTR + s_blk * PITCH;
    const float* kb = sK  + hloc * HSTR + t_blk * PITCH;
    ull acc[4][4];
#pragma unroll
    for (int kk = 0; kk < 4; kk++)
#pragma unroll
        for (int mm = 0; mm < 4; mm++) acc[kk][mm] = 0ull;

#pragma unroll
    for (int i = 0; i < 16; i++) {
        ulonglong2 q2[4], k2[4];
#pragma unroll
        for (int kk = 0; kk < 4; kk++)
            q2[kk] = *reinterpret_cast<const ulonglong2*>(qb + kk * (4 * PITCH) + 4 * i);
#pragma unroll
        for (int mm = 0; mm < 4; mm++)
            k2[mm] = *reinterpret_cast<const ulonglong2*>(kb + mm * (4 * PITCH) + 4 * i);
#pragma unroll
        for (int kk = 0; kk < 4; kk++)
#pragma unroll
            for (int mm = 0; mm < 4; mm++) {
                acc[kk][mm] = fma2(q2[kk].x, k2[mm].x, acc[kk][mm]);
                acc[kk][mm] = fma2(q2[kk].y, k2[mm].y, acc[kk][mm]);
            }
    }

    // ---- Issue ALL V loads now (independent; latency overlapped by softmax) ----
    float4 vreg[16];
    {
        const float4* gv = reinterpret_cast<const float4*>(v);
        const int base4 = blockIdx.x * (HPC * 256);
#pragma unroll
        for (int j = 0; j < 16; j++)
            vreg[j] = gv[base4 + j * NTHREADS + tid];
    }

    __syncwarp();   // all lanes done reading Q region before it becomes V

    // ---- Softmax per row (4 local + xor-shuffle over t_blk) + dropout ----
    float w[4][4];
#pragma unroll
    for (int kk = 0; kk < 4; kk++) {
        float e[4], sum = 0.f;
#pragma unroll
        for (int mm = 0; mm < 4; mm++) {
            float2 p = unpack2(acc[kk][mm]);
            e[mm] = __expf((p.x + p.y) * SCALE);   // logits ~N(0,8): skip max-sub
            sum += e[mm];
        }
        sum += __shfl_xor_sync(0xffffffffu, sum, 4, 16);
        sum += __shfl_xor_sync(0xffffffffu, sum, 8, 16);
        float inv = __fdividef(1.4285714285714286f, sum);   // (1/0.7)/sum
#pragma unroll
        for (int mm = 0; mm < 4; mm++)
            w[kk][mm] = ((keepmask >> (kk * 4 + mm)) & 1u) ? e[mm] * inv : 0.f;
    }

    // ---- Park V into the dead Q smem region (same padded layout) ----
#pragma unroll
    for (int j = 0; j < 16; j++) {
        int idx = j * NTHREADS + tid;
        int rem = idx & 255;
        int off = (idx >> 8) * HSTR + (rem >> 4) * PITCH + (rem & 15) * 4;
        *reinterpret_cast<float4*>(&sQV[off]) = vreg[j];
    }
    __syncwarp();

    // ---- Epilogue: all-LDS, SINGLE pass over all 4 quads ----
    ulonglong2* og = reinterpret_cast<ulonglong2*>(out) + (size_t)head * H_U2;
    const float* vb = sQV + hloc * HSTR;

    ull olo[4][4], ohi[4][4];                 // rows s_blk+4k x quads t_blk+4c
#pragma unroll
    for (int kk = 0; kk < 4; kk++)
#pragma unroll
        for (int cc = 0; cc < 4; cc++) { olo[kk][cc] = 0ull; ohi[kk][cc] = 0ull; }

#pragma unroll
    for (int t = 0; t < 16; t++) {
        int src = s_blk + 4 * (t & 3);        // lane holding w[.][t>>2] for our rows
        ull wp[4];
#pragma unroll
        for (int kk = 0; kk < 4; kk++)
            wp[kk] = pack2dup(__shfl_sync(0xffffffffu, w[kk][t >> 2], src, 16));
#pragma unroll
        for (int cc = 0; cc < 4; cc++) {
            ulonglong2 vv = *reinterpret_cast<const ulonglong2*>(
                vb + t * PITCH + (t_blk + 4 * cc) * 4);
#pragma unroll
            for (int kk = 0; kk < 4; kk++) {
                olo[kk][cc] = fma2(wp[kk], vv.x, olo[kk][cc]);
                ohi[kk][cc] = fma2(wp[kk], vv.y, ohi[kk][cc]);
            }
        }
    }

    // ---- Store: 16 float4s (rows s_blk+4k, quads t_blk+4c) ----
#pragma unroll
    for (int kk = 0; kk < 4; kk++)
#pragma unroll
        for (int cc = 0; cc < 4; cc++) {
            ulonglong2 val; val.x = olo[kk][cc]; val.y = ohi[kk][cc];
            og[(s_blk + 4 * kk) * 16 + t_blk + 4 * cc] = val;
        }
}

extern "C" void kernel_launch(void* const* d_in, const int* in_sizes, int n_in,
                              void* d_out, int out_size) {
    const float* q = (const float*)d_in[0];
    const float* k = (const float*)d_in[1];
    const float* v = (const float*)d_in[2];
    float* out = (float*)d_out;
    attn_dropout_kernel<<<8192 / HPC, NTHREADS>>>(q, k, v, out);
}